// round 14
// baseline (speedup 1.0000x reference)
#include <cuda_runtime.h>
#include <math.h>

// Problem dims
#define BSZ 256
#define TT  128
#define II  512
#define HH  1024
#define EE  256
// derived
#define FOURH 4096
#define FOURI 2048
#define HPI   1536   // H + I

// ---------------- scratch (static device allocations; no cudaMalloc) --------
__device__ float g_xproj[134217728];      // [T][B][4H] = 128*256*4096 floats (512MB)
__device__ float g_henc[2][BSZ * HH];     // encoder h ping-pong
__device__ float g_cenc[BSZ * HH];        // encoder c
__device__ float g_hdec[2][BSZ * II];     // decoder h ping-pong
__device__ float g_cdec[BSZ * II];        // decoder c
__device__ float g_wrec[FOURI * II];      // [2048][512] = dec_Wih[:,H:] + dec_Whh
__device__ float g_fixed[BSZ * FOURI];    // [256][2048] fixed decoder pre-activation
__device__ float g_dfh[BSZ * HH];         // [256][1024] dec_first_hidden

__device__ __forceinline__ float sigmoidf_(float x) {
    return 1.0f / (1.0f + expf(-x));
}

// ---------------- W_rec precompute ------------------------------------------
__global__ void wrec_kernel(const float* __restrict__ dWih,
                            const float* __restrict__ dWhh) {
    int i = blockIdx.x * blockDim.x + threadIdx.x;   // over 2048*512
    if (i < FOURI * II) {
        int j = i >> 9;          // row 0..2047
        int k = i & 511;         // col 0..511
        g_wrec[i] = dWih[j * HPI + HH + k] + dWhh[i];
    }
}

// ---------------- xproj GEMM: [32768 x 4096 x 512] --------------------------
// C row m = t*256 + b ;  A row = x[b][t][:]  (x is [B,T,I])
// BM=128, BN=128, BK=16, 256 threads, TM=TN=8
__global__ __launch_bounds__(256, 1)
void xproj_gemm(const float* __restrict__ x, const float* __restrict__ Wih,
                const float* __restrict__ bih, const float* __restrict__ bhh) {
    const int n0 = blockIdx.x * 128;        // over 4096
    const int m0 = blockIdx.y * 128;        // over 32768
    const int t  = m0 >> 8;                 // rows of a block share one t
    const int bb = m0 & 255;                // b base (0 or 128)

    __shared__ __align__(16) float As[16][132];
    __shared__ __align__(16) float Bs[16][132];

    const int tid = threadIdx.x;
    const int tx = tid & 15;
    const int ty = tid >> 4;

    const int lrow = tid >> 1;              // 0..127
    const int lc   = (tid & 1) * 8;         // 0 or 8
    const float* aptr = x + ((size_t)(bb + lrow) * TT + t) * II + lc;
    const float* bptr = Wih + (size_t)(n0 + lrow) * II + lc;

    float acc[8][8];
#pragma unroll
    for (int i = 0; i < 8; i++)
#pragma unroll
        for (int j = 0; j < 8; j++) acc[i][j] = 0.0f;

    for (int kt = 0; kt < II; kt += 16) {
        float4 a0 = *(const float4*)(aptr + kt);
        float4 a1 = *(const float4*)(aptr + kt + 4);
        float4 b0 = *(const float4*)(bptr + kt);
        float4 b1 = *(const float4*)(bptr + kt + 4);
        As[lc + 0][lrow] = a0.x; As[lc + 1][lrow] = a0.y;
        As[lc + 2][lrow] = a0.z; As[lc + 3][lrow] = a0.w;
        As[lc + 4][lrow] = a1.x; As[lc + 5][lrow] = a1.y;
        As[lc + 6][lrow] = a1.z; As[lc + 7][lrow] = a1.w;
        Bs[lc + 0][lrow] = b0.x; Bs[lc + 1][lrow] = b0.y;
        Bs[lc + 2][lrow] = b0.z; Bs[lc + 3][lrow] = b0.w;
        Bs[lc + 4][lrow] = b1.x; Bs[lc + 5][lrow] = b1.y;
        Bs[lc + 6][lrow] = b1.z; Bs[lc + 7][lrow] = b1.w;
        __syncthreads();
#pragma unroll
        for (int k = 0; k < 16; k++) {
            float4 av0 = *(const float4*)&As[k][ty * 8];
            float4 av1 = *(const float4*)&As[k][ty * 8 + 4];
            float4 bv0 = *(const float4*)&Bs[k][tx * 8];
            float4 bv1 = *(const float4*)&Bs[k][tx * 8 + 4];
            float ar[8] = {av0.x, av0.y, av0.z, av0.w, av1.x, av1.y, av1.z, av1.w};
            float br[8] = {bv0.x, bv0.y, bv0.z, bv0.w, bv1.x, bv1.y, bv1.z, bv1.w};
#pragma unroll
            for (int i = 0; i < 8; i++)
#pragma unroll
                for (int j = 0; j < 8; j++)
                    acc[i][j] = fmaf(ar[i], br[j], acc[i][j]);
        }
        __syncthreads();
    }

    float bsum[8];
#pragma unroll
    for (int j = 0; j < 8; j++) {
        int n = n0 + tx * 8 + j;
        bsum[j] = bih[n] + bhh[n];
    }
#pragma unroll
    for (int i = 0; i < 8; i++) {
        size_t m = (size_t)(m0 + ty * 8 + i);
        float* crow = g_xproj + m * FOURH + n0 + tx * 8;
#pragma unroll
        for (int j = 0; j < 8; j++) crow[j] = acc[i][j] + bsum[j];
    }
}

// ---------------- encoder recurrent step ------------------------------------
// pre = xproj[t] + h @ Whh^T ; fused gates ; update c, h
// BM=64 (batch), BN=128 = 4 gates x 32 j, BK=16, 256 thr, TM=4, TN=8
__global__ __launch_bounds__(256, 1)
void enc_step_kernel(const float* __restrict__ Whh, int t) {
    const int j0 = blockIdx.x * 32;         // 32 j-tiles over H=1024
    const int b0 = blockIdx.y * 64;         // 4 b-tiles over B=256
    const float* __restrict__ hin  = g_henc[t & 1];
    float* __restrict__ hout       = g_henc[(t + 1) & 1];
    const float* __restrict__ xadd = g_xproj + (size_t)t * (BSZ * FOURH);

    __shared__ __align__(16) float As[16][64];
    __shared__ __align__(16) float Bs[16][132];

    const int tid = threadIdx.x;
    const int tx = tid & 15;
    const int ty = tid >> 4;

    // A-tile loader: 64x16, 1 float4 per thread
    const int arow = tid >> 2;              // 0..63
    const int ac   = (tid & 3) * 4;
    const float* aptr = hin + (size_t)(b0 + arow) * HH + ac;
    // B-tile loader: 128 mapped rows x 16, 2 float4 per thread
    const int brow = tid >> 1;              // 0..127
    const int bc   = (tid & 1) * 8;
    const int gate = brow >> 5;
    const int jlb  = brow & 31;
    const float* bptr = Whh + (size_t)(gate * HH + j0 + jlb) * HH + bc;

    float acc[4][8];
#pragma unroll
    for (int i = 0; i < 4; i++)
#pragma unroll
        for (int j = 0; j < 8; j++) acc[i][j] = 0.0f;

    for (int kt = 0; kt < HH; kt += 16) {
        float4 av = *(const float4*)(aptr + kt);
        As[ac + 0][arow] = av.x; As[ac + 1][arow] = av.y;
        As[ac + 2][arow] = av.z; As[ac + 3][arow] = av.w;
        float4 bv0 = *(const float4*)(bptr + kt);
        float4 bv1 = *(const float4*)(bptr + kt + 4);
        Bs[bc + 0][brow] = bv0.x; Bs[bc + 1][brow] = bv0.y;
        Bs[bc + 2][brow] = bv0.z; Bs[bc + 3][brow] = bv0.w;
        Bs[bc + 4][brow] = bv1.x; Bs[bc + 5][brow] = bv1.y;
        Bs[bc + 6][brow] = bv1.z; Bs[bc + 7][brow] = bv1.w;
        __syncthreads();
#pragma unroll
        for (int k = 0; k < 16; k++) {
            float4 a = *(const float4*)&As[k][ty * 4];
            float4 bv0r = *(const float4*)&Bs[k][tx * 8];
            float4 bv1r = *(const float4*)&Bs[k][tx * 8 + 4];
            float ar[4] = {a.x, a.y, a.z, a.w};
            float br[8] = {bv0r.x, bv0r.y, bv0r.z, bv0r.w,
                           bv1r.x, bv1r.y, bv1r.z, bv1r.w};
#pragma unroll
            for (int i = 0; i < 4; i++)
#pragma unroll
                for (int j = 0; j < 8; j++)
                    acc[i][j] = fmaf(ar[i], br[j], acc[i][j]);
        }
        __syncthreads();
    }

    // epilogue: add xproj, exchange through smem, compute gates
    __shared__ float preS[64][129];
#pragma unroll
    for (int i = 0; i < 4; i++) {
        int r = ty * 4 + i;
#pragma unroll
        for (int j = 0; j < 8; j++) {
            int ccol = tx * 8 + j;
            int g = ccol >> 5, jl = ccol & 31;
            float xa = xadd[(size_t)(b0 + r) * FOURH + g * HH + j0 + jl];
            preS[r][ccol] = acc[i][j] + xa;
        }
    }
    __syncthreads();
    {
        int r = tid >> 2;                // 0..63
        int jb = (tid & 3) * 8;
        int b = b0 + r;
#pragma unroll
        for (int i = 0; i < 8; i++) {
            int jl = jb + i;
            float iv = sigmoidf_(preS[r][jl]);
            float fv = sigmoidf_(preS[r][32 + jl]);
            float gv = tanhf(preS[r][64 + jl]);
            float ov = sigmoidf_(preS[r][96 + jl]);
            size_t idx = (size_t)b * HH + j0 + jl;
            float cn = fv * g_cenc[idx] + iv * gv;
            g_cenc[idx] = cn;
            hout[idx] = ov * tanhf(cn);
        }
    }
}

// ---------------- decoder recurrent step ------------------------------------
// pre = fixed + h @ W_rec^T ; gates ; update c, h ; write out reversed
// BM=32, BN=128 = 4 gates x 32 j, BK=16, 256 thr, TM=2, TN=8
__global__ __launch_bounds__(256, 1)
void dec_step_kernel(float* __restrict__ out, int t) {
    const int j0 = blockIdx.x * 32;         // 16 j-tiles over I=512
    const int b0 = blockIdx.y * 32;         // 8 b-tiles over B=256
    const float* __restrict__ hin = g_hdec[t & 1];
    float* __restrict__ hout      = g_hdec[(t + 1) & 1];

    __shared__ __align__(16) float As[16][32];
    __shared__ __align__(16) float Bs[16][132];

    const int tid = threadIdx.x;
    const int tx = tid & 15;
    const int ty = tid >> 4;

    const int arow = tid >> 3;              // 0..31
    const int ac   = (tid & 7) * 2;
    const float* aptr = hin + (size_t)(b0 + arow) * II + ac;
    const int brow = tid >> 1;              // 0..127
    const int bc   = (tid & 1) * 8;
    const int gate = brow >> 5;
    const int jlb  = brow & 31;
    const float* bptr = g_wrec + (size_t)(gate * II + j0 + jlb) * II + bc;

    float acc[2][8];
#pragma unroll
    for (int i = 0; i < 2; i++)
#pragma unroll
        for (int j = 0; j < 8; j++) acc[i][j] = 0.0f;

    for (int kt = 0; kt < II; kt += 16) {
        float2 av = *(const float2*)(aptr + kt);
        As[ac + 0][arow] = av.x; As[ac + 1][arow] = av.y;
        float4 bv0 = *(const float4*)(bptr + kt);
        float4 bv1 = *(const float4*)(bptr + kt + 4);
        Bs[bc + 0][brow] = bv0.x; Bs[bc + 1][brow] = bv0.y;
        Bs[bc + 2][brow] = bv0.z; Bs[bc + 3][brow] = bv0.w;
        Bs[bc + 4][brow] = bv1.x; Bs[bc + 5][brow] = bv1.y;
        Bs[bc + 6][brow] = bv1.z; Bs[bc + 7][brow] = bv1.w;
        __syncthreads();
#pragma unroll
        for (int k = 0; k < 16; k++) {
            float2 a = *(const float2*)&As[k][ty * 2];
            float4 bv0r = *(const float4*)&Bs[k][tx * 8];
            float4 bv1r = *(const float4*)&Bs[k][tx * 8 + 4];
            float ar[2] = {a.x, a.y};
            float br[8] = {bv0r.x, bv0r.y, bv0r.z, bv0r.w,
                           bv1r.x, bv1r.y, bv1r.z, bv1r.w};
#pragma unroll
            for (int i = 0; i < 2; i++)
#pragma unroll
                for (int j = 0; j < 8; j++)
                    acc[i][j] = fmaf(ar[i], br[j], acc[i][j]);
        }
        __syncthreads();
    }

    __shared__ float preS[32][129];
#pragma unroll
    for (int i = 0; i < 2; i++) {
        int r = ty * 2 + i;
#pragma unroll
        for (int j = 0; j < 8; j++) {
            int ccol = tx * 8 + j;
            int g = ccol >> 5, jl = ccol & 31;
            float fx = g_fixed[(size_t)(b0 + r) * FOURI + g * II + j0 + jl];
            preS[r][ccol] = acc[i][j] + fx;
        }
    }
    __syncthreads();
    {
        int r = tid >> 3;               // 0..31
        int jb = (tid & 7) * 4;
        int b = b0 + r;
#pragma unroll
        for (int i = 0; i < 4; i++) {
            int jl = jb + i;
            float iv = sigmoidf_(preS[r][jl]);
            float fv = sigmoidf_(preS[r][32 + jl]);
            float gv = tanhf(preS[r][64 + jl]);
            float ov = sigmoidf_(preS[r][96 + jl]);
            size_t idx = (size_t)b * II + j0 + jl;
            float cn = fv * g_cdec[idx] + iv * gv;
            g_cdec[idx] = cn;
            float hn = ov * tanhf(cn);
            hout[idx] = hn;
            out[((size_t)b * TT + (TT - 1 - t)) * II + j0 + jl] = hn;
        }
    }
}

// ---------------- generic small GEMM: C = act(A @ Bw^T + b1 [+ b2]) ---------
// BM=64, BN=128, BK=16, 256 thr, TM=4, TN=8. M%64==0, N%128==0, K%16==0.
template <bool RELU, bool HASB2>
__global__ __launch_bounds__(256, 1)
void gemm_bias_kernel(const float* __restrict__ A, int lda,
                      const float* __restrict__ Bw, int ldb,
                      const float* __restrict__ b1, const float* __restrict__ b2,
                      float* __restrict__ C, int ldc, int K) {
    const int n0 = blockIdx.x * 128;
    const int m0 = blockIdx.y * 64;

    __shared__ __align__(16) float As[16][64];
    __shared__ __align__(16) float Bs[16][132];

    const int tid = threadIdx.x;
    const int tx = tid & 15;
    const int ty = tid >> 4;

    const int arow = tid >> 2;
    const int ac   = (tid & 3) * 4;
    const float* aptr = A + (size_t)(m0 + arow) * lda + ac;
    const int brow = tid >> 1;
    const int bc   = (tid & 1) * 8;
    const float* bptr = Bw + (size_t)(n0 + brow) * ldb + bc;

    float acc[4][8];
#pragma unroll
    for (int i = 0; i < 4; i++)
#pragma unroll
        for (int j = 0; j < 8; j++) acc[i][j] = 0.0f;

    for (int kt = 0; kt < K; kt += 16) {
        float4 av = *(const float4*)(aptr + kt);
        As[ac + 0][arow] = av.x; As[ac + 1][arow] = av.y;
        As[ac + 2][arow] = av.z; As[ac + 3][arow] = av.w;
        float4 bv0 = *(const float4*)(bptr + kt);
        float4 bv1 = *(const float4*)(bptr + kt + 4);
        Bs[bc + 0][brow] = bv0.x; Bs[bc + 1][brow] = bv0.y;
        Bs[bc + 2][brow] = bv0.z; Bs[bc + 3][brow] = bv0.w;
        Bs[bc + 4][brow] = bv1.x; Bs[bc + 5][brow] = bv1.y;
        Bs[bc + 6][brow] = bv1.z; Bs[bc + 7][brow] = bv1.w;
        __syncthreads();
#pragma unroll
        for (int k = 0; k < 16; k++) {
            float4 a = *(const float4*)&As[k][ty * 4];
            float4 bv0r = *(const float4*)&Bs[k][tx * 8];
            float4 bv1r = *(const float4*)&Bs[k][tx * 8 + 4];
            float ar[4] = {a.x, a.y, a.z, a.w};
            float br[8] = {bv0r.x, bv0r.y, bv0r.z, bv0r.w,
                           bv1r.x, bv1r.y, bv1r.z, bv1r.w};
#pragma unroll
            for (int i = 0; i < 4; i++)
#pragma unroll
                for (int j = 0; j < 8; j++)
                    acc[i][j] = fmaf(ar[i], br[j], acc[i][j]);
        }
        __syncthreads();
    }

#pragma unroll
    for (int j = 0; j < 8; j++) {
        int n = n0 + tx * 8 + j;
        float bias = b1[n];
        if (HASB2) bias += b2[n];
#pragma unroll
        for (int i = 0; i < 4; i++) {
            float v = acc[i][j] + bias;
            if (RELU) v = fmaxf(v, 0.0f);
            C[(size_t)(m0 + ty * 4 + i) * ldc + n] = v;
        }
    }
}

// ---------------- launcher ---------------------------------------------------
extern "C" void kernel_launch(void* const* d_in, const int* in_sizes, int n_in,
                              void* d_out, int out_size) {
    const float* x        = (const float*)d_in[0];
    const float* enc_Wih  = (const float*)d_in[1];
    const float* enc_Whh  = (const float*)d_in[2];
    const float* enc_bih  = (const float*)d_in[3];
    const float* enc_bhh  = (const float*)d_in[4];
    const float* encfc_W  = (const float*)d_in[5];
    const float* encfc_b  = (const float*)d_in[6];
    const float* decfc_W  = (const float*)d_in[7];
    const float* decfc_b  = (const float*)d_in[8];
    const float* dec_Wih  = (const float*)d_in[9];
    const float* dec_Whh  = (const float*)d_in[10];
    const float* dec_bih  = (const float*)d_in[11];
    const float* dec_bhh  = (const float*)d_in[12];
    float* out = (float*)d_out;
    float* embd = out + (size_t)BSZ * TT * II;   // outputs first, then embd

    // scratch symbol addresses (cheap, capture-safe, recomputed every call)
    void *p_henc, *p_cenc, *p_hdec, *p_cdec, *p_dfh, *p_fixed;
    cudaGetSymbolAddress(&p_henc, g_henc);
    cudaGetSymbolAddress(&p_cenc, g_cenc);
    cudaGetSymbolAddress(&p_hdec, g_hdec);
    cudaGetSymbolAddress(&p_cdec, g_cdec);
    cudaGetSymbolAddress(&p_dfh, g_dfh);
    cudaGetSymbolAddress(&p_fixed, g_fixed);

    // zero initial states (only ping-pong buffer 0 of h; c fully)
    cudaMemsetAsync(p_henc, 0, (size_t)BSZ * HH * sizeof(float));
    cudaMemsetAsync(p_cenc, 0, (size_t)BSZ * HH * sizeof(float));
    cudaMemsetAsync(p_hdec, 0, (size_t)BSZ * II * sizeof(float));
    cudaMemsetAsync(p_cdec, 0, (size_t)BSZ * II * sizeof(float));

    // W_rec = dec_Wih[:, H:] + dec_Whh
    wrec_kernel<<<(FOURI * II + 255) / 256, 256>>>(dec_Wih, dec_Whh);

    // xproj[t][b][:] = x[b][t][:] @ enc_Wih^T + (bih + bhh)
    xproj_gemm<<<dim3(FOURH / 128, (TT * BSZ) / 128), 256>>>(x, enc_Wih, enc_bih, enc_bhh);

    // encoder recurrence
    for (int t = 0; t < TT; t++)
        enc_step_kernel<<<dim3(HH / 32, BSZ / 64), 256>>>(enc_Whh, t);

    // embd = relu(c_final @ encfc_W^T + encfc_b)   [256 x 256]
    gemm_bias_kernel<true, false><<<dim3(EE / 128, BSZ / 64), 256>>>(
        (const float*)p_cenc, HH, encfc_W, HH, encfc_b, nullptr, embd, EE, HH);

    // dec_first_hidden = relu(embd @ decfc_W^T + decfc_b)  [256 x 1024]
    gemm_bias_kernel<true, false><<<dim3(HH / 128, BSZ / 64), 256>>>(
        (const float*)embd, EE, decfc_W, EE, decfc_b, nullptr, (float*)p_dfh, HH, EE);

    // fixed = dfh @ dec_Wih[:, :H]^T + (dec_bih + dec_bhh)  [256 x 2048]
    gemm_bias_kernel<false, true><<<dim3(FOURI / 128, BSZ / 64), 256>>>(
        (const float*)p_dfh, HH, dec_Wih, HPI, dec_bih, dec_bhh, (float*)p_fixed, FOURI, HH);

    // decoder recurrence (writes outputs reversed)
    for (int t = 0; t < TT; t++)
        dec_step_kernel<<<dim3(II / 32, BSZ / 32), 256>>>(out, t);
}

// round 15
// speedup vs baseline: 1.0005x; 1.0005x over previous
#include <cuda_runtime.h>
#include <math.h>

// Problem dims
#define BSZ 256
#define TT  128
#define II  512
#define HH  1024
#define EE  256
// derived
#define FOURH 4096
#define FOURI 2048
#define HPI   1536   // H + I

// ---------------- scratch (static device allocations; no cudaMalloc) --------
__device__ float g_xproj[134217728];      // [T][B][4H] = 128*256*4096 floats (512MB)
__device__ float g_henc[2][BSZ * HH];     // encoder h ping-pong
__device__ float g_cenc[BSZ * HH];        // encoder c
__device__ float g_hdec[2][BSZ * II];     // decoder h ping-pong
__device__ float g_cdec[BSZ * II];        // decoder c
__device__ float g_wrec[FOURI * II];      // [2048][512] = dec_Wih[:,H:] + dec_Whh
__device__ float g_fixed[BSZ * FOURI];    // [256][2048] fixed decoder pre-activation
__device__ float g_dfh[BSZ * HH];         // [256][1024] dec_first_hidden

__device__ __forceinline__ float sigmoidf_(float x) {
    return 1.0f / (1.0f + expf(-x));
}

// ---------------- W_rec precompute ------------------------------------------
__global__ void wrec_kernel(const float* __restrict__ dWih,
                            const float* __restrict__ dWhh) {
    int i = blockIdx.x * blockDim.x + threadIdx.x;   // over 2048*512
    if (i < FOURI * II) {
        int j = i >> 9;          // row 0..2047
        int k = i & 511;         // col 0..511
        g_wrec[i] = dWih[j * HPI + HH + k] + dWhh[i];
    }
}

// ---------------- xproj GEMM: [32768 x 4096 x 512] --------------------------
// C row m = t*256 + b ;  A row = x[b][t][:]  (x is [B,T,I])
// BM=128, BN=128, BK=16, 256 threads, TM=TN=8
__global__ __launch_bounds__(256, 1)
void xproj_gemm(const float* __restrict__ x, const float* __restrict__ Wih,
                const float* __restrict__ bih, const float* __restrict__ bhh) {
    const int n0 = blockIdx.x * 128;        // over 4096
    const int m0 = blockIdx.y * 128;        // over 32768
    const int t  = m0 >> 8;                 // rows of a block share one t
    const int bb = m0 & 255;                // b base (0 or 128)

    __shared__ __align__(16) float As[16][132];
    __shared__ __align__(16) float Bs[16][132];

    const int tid = threadIdx.x;
    const int tx = tid & 15;
    const int ty = tid >> 4;

    const int lrow = tid >> 1;              // 0..127
    const int lc   = (tid & 1) * 8;         // 0 or 8
    const float* aptr = x + ((size_t)(bb + lrow) * TT + t) * II + lc;
    const float* bptr = Wih + (size_t)(n0 + lrow) * II + lc;

    float acc[8][8];
#pragma unroll
    for (int i = 0; i < 8; i++)
#pragma unroll
        for (int j = 0; j < 8; j++) acc[i][j] = 0.0f;

    for (int kt = 0; kt < II; kt += 16) {
        float4 a0 = *(const float4*)(aptr + kt);
        float4 a1 = *(const float4*)(aptr + kt + 4);
        float4 b0 = *(const float4*)(bptr + kt);
        float4 b1 = *(const float4*)(bptr + kt + 4);
        As[lc + 0][lrow] = a0.x; As[lc + 1][lrow] = a0.y;
        As[lc + 2][lrow] = a0.z; As[lc + 3][lrow] = a0.w;
        As[lc + 4][lrow] = a1.x; As[lc + 5][lrow] = a1.y;
        As[lc + 6][lrow] = a1.z; As[lc + 7][lrow] = a1.w;
        Bs[lc + 0][lrow] = b0.x; Bs[lc + 1][lrow] = b0.y;
        Bs[lc + 2][lrow] = b0.z; Bs[lc + 3][lrow] = b0.w;
        Bs[lc + 4][lrow] = b1.x; Bs[lc + 5][lrow] = b1.y;
        Bs[lc + 6][lrow] = b1.z; Bs[lc + 7][lrow] = b1.w;
        __syncthreads();
#pragma unroll
        for (int k = 0; k < 16; k++) {
            float4 av0 = *(const float4*)&As[k][ty * 8];
            float4 av1 = *(const float4*)&As[k][ty * 8 + 4];
            float4 bv0 = *(const float4*)&Bs[k][tx * 8];
            float4 bv1 = *(const float4*)&Bs[k][tx * 8 + 4];
            float ar[8] = {av0.x, av0.y, av0.z, av0.w, av1.x, av1.y, av1.z, av1.w};
            float br[8] = {bv0.x, bv0.y, bv0.z, bv0.w, bv1.x, bv1.y, bv1.z, bv1.w};
#pragma unroll
            for (int i = 0; i < 8; i++)
#pragma unroll
                for (int j = 0; j < 8; j++)
                    acc[i][j] = fmaf(ar[i], br[j], acc[i][j]);
        }
        __syncthreads();
    }

    float bsum[8];
#pragma unroll
    for (int j = 0; j < 8; j++) {
        int n = n0 + tx * 8 + j;
        bsum[j] = bih[n] + bhh[n];
    }
#pragma unroll
    for (int i = 0; i < 8; i++) {
        size_t m = (size_t)(m0 + ty * 8 + i);
        float* crow = g_xproj + m * FOURH + n0 + tx * 8;
#pragma unroll
        for (int j = 0; j < 8; j++) crow[j] = acc[i][j] + bsum[j];
    }
}

// ---------------- encoder recurrent step ------------------------------------
// pre = xproj[t] + h @ Whh^T ; fused gates ; update c, h
// BM=64 (batch), BN=128 = 4 gates x 32 j, BK=16, 256 thr, TM=4, TN=8
__global__ __launch_bounds__(256, 1)
void enc_step_kernel(const float* __restrict__ Whh, int t) {
    const int j0 = blockIdx.x * 32;         // 32 j-tiles over H=1024
    const int b0 = blockIdx.y * 64;         // 4 b-tiles over B=256
    const float* __restrict__ hin  = g_henc[t & 1];
    float* __restrict__ hout       = g_henc[(t + 1) & 1];
    const float* __restrict__ xadd = g_xproj + (size_t)t * (BSZ * FOURH);

    __shared__ __align__(16) float As[16][64];
    __shared__ __align__(16) float Bs[16][132];

    const int tid = threadIdx.x;
    const int tx = tid & 15;
    const int ty = tid >> 4;

    // A-tile loader: 64x16, 1 float4 per thread
    const int arow = tid >> 2;              // 0..63
    const int ac   = (tid & 3) * 4;
    const float* aptr = hin + (size_t)(b0 + arow) * HH + ac;
    // B-tile loader: 128 mapped rows x 16, 2 float4 per thread
    const int brow = tid >> 1;              // 0..127
    const int bc   = (tid & 1) * 8;
    const int gate = brow >> 5;
    const int jlb  = brow & 31;
    const float* bptr = Whh + (size_t)(gate * HH + j0 + jlb) * HH + bc;

    float acc[4][8];
#pragma unroll
    for (int i = 0; i < 4; i++)
#pragma unroll
        for (int j = 0; j < 8; j++) acc[i][j] = 0.0f;

    for (int kt = 0; kt < HH; kt += 16) {
        float4 av = *(const float4*)(aptr + kt);
        As[ac + 0][arow] = av.x; As[ac + 1][arow] = av.y;
        As[ac + 2][arow] = av.z; As[ac + 3][arow] = av.w;
        float4 bv0 = *(const float4*)(bptr + kt);
        float4 bv1 = *(const float4*)(bptr + kt + 4);
        Bs[bc + 0][brow] = bv0.x; Bs[bc + 1][brow] = bv0.y;
        Bs[bc + 2][brow] = bv0.z; Bs[bc + 3][brow] = bv0.w;
        Bs[bc + 4][brow] = bv1.x; Bs[bc + 5][brow] = bv1.y;
        Bs[bc + 6][brow] = bv1.z; Bs[bc + 7][brow] = bv1.w;
        __syncthreads();
#pragma unroll
        for (int k = 0; k < 16; k++) {
            float4 a = *(const float4*)&As[k][ty * 4];
            float4 bv0r = *(const float4*)&Bs[k][tx * 8];
            float4 bv1r = *(const float4*)&Bs[k][tx * 8 + 4];
            float ar[4] = {a.x, a.y, a.z, a.w};
            float br[8] = {bv0r.x, bv0r.y, bv0r.z, bv0r.w,
                           bv1r.x, bv1r.y, bv1r.z, bv1r.w};
#pragma unroll
            for (int i = 0; i < 4; i++)
#pragma unroll
                for (int j = 0; j < 8; j++)
                    acc[i][j] = fmaf(ar[i], br[j], acc[i][j]);
        }
        __syncthreads();
    }

    // epilogue: add xproj, exchange through smem, compute gates
    __shared__ float preS[64][129];
#pragma unroll
    for (int i = 0; i < 4; i++) {
        int r = ty * 4 + i;
#pragma unroll
        for (int j = 0; j < 8; j++) {
            int ccol = tx * 8 + j;
            int g = ccol >> 5, jl = ccol & 31;
            float xa = xadd[(size_t)(b0 + r) * FOURH + g * HH + j0 + jl];
            preS[r][ccol] = acc[i][j] + xa;
        }
    }
    __syncthreads();
    {
        int r = tid >> 2;                // 0..63
        int jb = (tid & 3) * 8;
        int b = b0 + r;
#pragma unroll
        for (int i = 0; i < 8; i++) {
            int jl = jb + i;
            float iv = sigmoidf_(preS[r][jl]);
            float fv = sigmoidf_(preS[r][32 + jl]);
            float gv = tanhf(preS[r][64 + jl]);
            float ov = sigmoidf_(preS[r][96 + jl]);
            size_t idx = (size_t)b * HH + j0 + jl;
            float cn = fv * g_cenc[idx] + iv * gv;
            g_cenc[idx] = cn;
            hout[idx] = ov * tanhf(cn);
        }
    }
}

// ---------------- decoder recurrent step ------------------------------------
// pre = fixed + h @ W_rec^T ; gates ; update c, h ; write out reversed
// BM=32, BN=128 = 4 gates x 32 j, BK=16, 256 thr, TM=2, TN=8
__global__ __launch_bounds__(256, 1)
void dec_step_kernel(float* __restrict__ out, int t) {
    const int j0 = blockIdx.x * 32;         // 16 j-tiles over I=512
    const int b0 = blockIdx.y * 32;         // 8 b-tiles over B=256
    const float* __restrict__ hin = g_hdec[t & 1];
    float* __restrict__ hout      = g_hdec[(t + 1) & 1];

    __shared__ __align__(16) float As[16][32];
    __shared__ __align__(16) float Bs[16][132];

    const int tid = threadIdx.x;
    const int tx = tid & 15;
    const int ty = tid >> 4;

    const int arow = tid >> 3;              // 0..31
    const int ac   = (tid & 7) * 2;
    const float* aptr = hin + (size_t)(b0 + arow) * II + ac;
    const int brow = tid >> 1;              // 0..127
    const int bc   = (tid & 1) * 8;
    const int gate = brow >> 5;
    const int jlb  = brow & 31;
    const float* bptr = g_wrec + (size_t)(gate * II + j0 + jlb) * II + bc;

    float acc[2][8];
#pragma unroll
    for (int i = 0; i < 2; i++)
#pragma unroll
        for (int j = 0; j < 8; j++) acc[i][j] = 0.0f;

    for (int kt = 0; kt < II; kt += 16) {
        float2 av = *(const float2*)(aptr + kt);
        As[ac + 0][arow] = av.x; As[ac + 1][arow] = av.y;
        float4 bv0 = *(const float4*)(bptr + kt);
        float4 bv1 = *(const float4*)(bptr + kt + 4);
        Bs[bc + 0][brow] = bv0.x; Bs[bc + 1][brow] = bv0.y;
        Bs[bc + 2][brow] = bv0.z; Bs[bc + 3][brow] = bv0.w;
        Bs[bc + 4][brow] = bv1.x; Bs[bc + 5][brow] = bv1.y;
        Bs[bc + 6][brow] = bv1.z; Bs[bc + 7][brow] = bv1.w;
        __syncthreads();
#pragma unroll
        for (int k = 0; k < 16; k++) {
            float2 a = *(const float2*)&As[k][ty * 2];
            float4 bv0r = *(const float4*)&Bs[k][tx * 8];
            float4 bv1r = *(const float4*)&Bs[k][tx * 8 + 4];
            float ar[2] = {a.x, a.y};
            float br[8] = {bv0r.x, bv0r.y, bv0r.z, bv0r.w,
                           bv1r.x, bv1r.y, bv1r.z, bv1r.w};
#pragma unroll
            for (int i = 0; i < 2; i++)
#pragma unroll
                for (int j = 0; j < 8; j++)
                    acc[i][j] = fmaf(ar[i], br[j], acc[i][j]);
        }
        __syncthreads();
    }

    __shared__ float preS[32][129];
#pragma unroll
    for (int i = 0; i < 2; i++) {
        int r = ty * 2 + i;
#pragma unroll
        for (int j = 0; j < 8; j++) {
            int ccol = tx * 8 + j;
            int g = ccol >> 5, jl = ccol & 31;
            float fx = g_fixed[(size_t)(b0 + r) * FOURI + g * II + j0 + jl];
            preS[r][ccol] = acc[i][j] + fx;
        }
    }
    __syncthreads();
    {
        int r = tid >> 3;               // 0..31
        int jb = (tid & 7) * 4;
        int b = b0 + r;
#pragma unroll
        for (int i = 0; i < 4; i++) {
            int jl = jb + i;
            float iv = sigmoidf_(preS[r][jl]);
            float fv = sigmoidf_(preS[r][32 + jl]);
            float gv = tanhf(preS[r][64 + jl]);
            float ov = sigmoidf_(preS[r][96 + jl]);
            size_t idx = (size_t)b * II + j0 + jl;
            float cn = fv * g_cdec[idx] + iv * gv;
            g_cdec[idx] = cn;
            float hn = ov * tanhf(cn);
            hout[idx] = hn;
            out[((size_t)b * TT + (TT - 1 - t)) * II + j0 + jl] = hn;
        }
    }
}

// ---------------- generic small GEMM: C = act(A @ Bw^T + b1 [+ b2]) ---------
// BM=64, BN=128, BK=16, 256 thr, TM=4, TN=8. M%64==0, N%128==0, K%16==0.
template <bool RELU, bool HASB2>
__global__ __launch_bounds__(256, 1)
void gemm_bias_kernel(const float* __restrict__ A, int lda,
                      const float* __restrict__ Bw, int ldb,
                      const float* __restrict__ b1, const float* __restrict__ b2,
                      float* __restrict__ C, int ldc, int K) {
    const int n0 = blockIdx.x * 128;
    const int m0 = blockIdx.y * 64;

    __shared__ __align__(16) float As[16][64];
    __shared__ __align__(16) float Bs[16][132];

    const int tid = threadIdx.x;
    const int tx = tid & 15;
    const int ty = tid >> 4;

    const int arow = tid >> 2;
    const int ac   = (tid & 3) * 4;
    const float* aptr = A + (size_t)(m0 + arow) * lda + ac;
    const int brow = tid >> 1;
    const int bc   = (tid & 1) * 8;
    const float* bptr = Bw + (size_t)(n0 + brow) * ldb + bc;

    float acc[4][8];
#pragma unroll
    for (int i = 0; i < 4; i++)
#pragma unroll
        for (int j = 0; j < 8; j++) acc[i][j] = 0.0f;

    for (int kt = 0; kt < K; kt += 16) {
        float4 av = *(const float4*)(aptr + kt);
        As[ac + 0][arow] = av.x; As[ac + 1][arow] = av.y;
        As[ac + 2][arow] = av.z; As[ac + 3][arow] = av.w;
        float4 bv0 = *(const float4*)(bptr + kt);
        float4 bv1 = *(const float4*)(bptr + kt + 4);
        Bs[bc + 0][brow] = bv0.x; Bs[bc + 1][brow] = bv0.y;
        Bs[bc + 2][brow] = bv0.z; Bs[bc + 3][brow] = bv0.w;
        Bs[bc + 4][brow] = bv1.x; Bs[bc + 5][brow] = bv1.y;
        Bs[bc + 6][brow] = bv1.z; Bs[bc + 7][brow] = bv1.w;
        __syncthreads();
#pragma unroll
        for (int k = 0; k < 16; k++) {
            float4 a = *(const float4*)&As[k][ty * 4];
            float4 bv0r = *(const float4*)&Bs[k][tx * 8];
            float4 bv1r = *(const float4*)&Bs[k][tx * 8 + 4];
            float ar[4] = {a.x, a.y, a.z, a.w};
            float br[8] = {bv0r.x, bv0r.y, bv0r.z, bv0r.w,
                           bv1r.x, bv1r.y, bv1r.z, bv1r.w};
#pragma unroll
            for (int i = 0; i < 4; i++)
#pragma unroll
                for (int j = 0; j < 8; j++)
                    acc[i][j] = fmaf(ar[i], br[j], acc[i][j]);
        }
        __syncthreads();
    }

#pragma unroll
    for (int j = 0; j < 8; j++) {
        int n = n0 + tx * 8 + j;
        float bias = b1[n];
        if (HASB2) bias += b2[n];
#pragma unroll
        for (int i = 0; i < 4; i++) {
            float v = acc[i][j] + bias;
            if (RELU) v = fmaxf(v, 0.0f);
            C[(size_t)(m0 + ty * 4 + i) * ldc + n] = v;
        }
    }
}

// ---------------- launcher ---------------------------------------------------
extern "C" void kernel_launch(void* const* d_in, const int* in_sizes, int n_in,
                              void* d_out, int out_size) {
    const float* x        = (const float*)d_in[0];
    const float* enc_Wih  = (const float*)d_in[1];
    const float* enc_Whh  = (const float*)d_in[2];
    const float* enc_bih  = (const float*)d_in[3];
    const float* enc_bhh  = (const float*)d_in[4];
    const float* encfc_W  = (const float*)d_in[5];
    const float* encfc_b  = (const float*)d_in[6];
    const float* decfc_W  = (const float*)d_in[7];
    const float* decfc_b  = (const float*)d_in[8];
    const float* dec_Wih  = (const float*)d_in[9];
    const float* dec_Whh  = (const float*)d_in[10];
    const float* dec_bih  = (const float*)d_in[11];
    const float* dec_bhh  = (const float*)d_in[12];
    float* out = (float*)d_out;
    float* embd = out + (size_t)BSZ * TT * II;   // outputs first, then embd

    // scratch symbol addresses (cheap, capture-safe, recomputed every call)
    void *p_henc, *p_cenc, *p_hdec, *p_cdec, *p_dfh, *p_fixed;
    cudaGetSymbolAddress(&p_henc, g_henc);
    cudaGetSymbolAddress(&p_cenc, g_cenc);
    cudaGetSymbolAddress(&p_hdec, g_hdec);
    cudaGetSymbolAddress(&p_cdec, g_cdec);
    cudaGetSymbolAddress(&p_dfh, g_dfh);
    cudaGetSymbolAddress(&p_fixed, g_fixed);

    // zero initial states (only ping-pong buffer 0 of h; c fully)
    cudaMemsetAsync(p_henc, 0, (size_t)BSZ * HH * sizeof(float));
    cudaMemsetAsync(p_cenc, 0, (size_t)BSZ * HH * sizeof(float));
    cudaMemsetAsync(p_hdec, 0, (size_t)BSZ * II * sizeof(float));
    cudaMemsetAsync(p_cdec, 0, (size_t)BSZ * II * sizeof(float));

    // W_rec = dec_Wih[:, H:] + dec_Whh
    wrec_kernel<<<(FOURI * II + 255) / 256, 256>>>(dec_Wih, dec_Whh);

    // xproj[t][b][:] = x[b][t][:] @ enc_Wih^T + (bih + bhh)
    xproj_gemm<<<dim3(FOURH / 128, (TT * BSZ) / 128), 256>>>(x, enc_Wih, enc_bih, enc_bhh);

    // encoder recurrence
    for (int t = 0; t < TT; t++)
        enc_step_kernel<<<dim3(HH / 32, BSZ / 64), 256>>>(enc_Whh, t);

    // embd = relu(c_final @ encfc_W^T + encfc_b)   [256 x 256]
    gemm_bias_kernel<true, false><<<dim3(EE / 128, BSZ / 64), 256>>>(
        (const float*)p_cenc, HH, encfc_W, HH, encfc_b, nullptr, embd, EE, HH);

    // dec_first_hidden = relu(embd @ decfc_W^T + decfc_b)  [256 x 1024]
    gemm_bias_kernel<true, false><<<dim3(HH / 128, BSZ / 64), 256>>>(
        (const float*)embd, EE, decfc_W, EE, decfc_b, nullptr, (float*)p_dfh, HH, EE);

    // fixed = dfh @ dec_Wih[:, :H]^T + (dec_bih + dec_bhh)  [256 x 2048]
    gemm_bias_kernel<false, true><<<dim3(FOURI / 128, BSZ / 64), 256>>>(
        (const float*)p_dfh, HH, dec_Wih, HPI, dec_bih, dec_bhh, (float*)p_fixed, FOURI, HH);

    // decoder recurrence (writes outputs reversed)
    for (int t = 0; t < TT; t++)
        dec_step_kernel<<<dim3(II / 32, BSZ / 32), 256>>>(out, t);
}

// round 16
// speedup vs baseline: 1.0016x; 1.0012x over previous
#include <cuda_runtime.h>
#include <math.h>

// Problem dims
#define BSZ 256
#define TT  128
#define II  512
#define HH  1024
#define EE  256
// derived
#define FOURH 4096
#define FOURI 2048
#define HPI   1536   // H + I

// ---------------- scratch (static device allocations; no cudaMalloc) --------
__device__ float g_xproj[134217728];      // [T][B][4H] = 128*256*4096 floats (512MB)
__device__ float g_henc[2][BSZ * HH];     // encoder h ping-pong
__device__ float g_cenc[BSZ * HH];        // encoder c
__device__ float g_hdec[2][BSZ * II];     // decoder h ping-pong
__device__ float g_cdec[BSZ * II];        // decoder c
__device__ float g_wrec[FOURI * II];      // [2048][512] = dec_Wih[:,H:] + dec_Whh
__device__ float g_fixed[BSZ * FOURI];    // [256][2048] fixed decoder pre-activation
__device__ float g_dfh[BSZ * HH];         // [256][1024] dec_first_hidden

__device__ __forceinline__ float sigmoidf_(float x) {
    return 1.0f / (1.0f + expf(-x));
}

// ---------------- W_rec precompute ------------------------------------------
__global__ void wrec_kernel(const float* __restrict__ dWih,
                            const float* __restrict__ dWhh) {
    int i = blockIdx.x * blockDim.x + threadIdx.x;   // over 2048*512
    if (i < FOURI * II) {
        int j = i >> 9;          // row 0..2047
        int k = i & 511;         // col 0..511
        g_wrec[i] = dWih[j * HPI + HH + k] + dWhh[i];
    }
}

// ---------------- xproj GEMM: [32768 x 4096 x 512] --------------------------
// C row m = t*256 + b ;  A row = x[b][t][:]  (x is [B,T,I])
// BM=128, BN=128, BK=16, 256 threads, TM=TN=8
__global__ __launch_bounds__(256, 1)
void xproj_gemm(const float* __restrict__ x, const float* __restrict__ Wih,
                const float* __restrict__ bih, const float* __restrict__ bhh) {
    const int n0 = blockIdx.x * 128;        // over 4096
    const int m0 = blockIdx.y * 128;        // over 32768
    const int t  = m0 >> 8;                 // rows of a block share one t
    const int bb = m0 & 255;                // b base (0 or 128)

    __shared__ __align__(16) float As[16][132];
    __shared__ __align__(16) float Bs[16][132];

    const int tid = threadIdx.x;
    const int tx = tid & 15;
    const int ty = tid >> 4;

    const int lrow = tid >> 1;              // 0..127
    const int lc   = (tid & 1) * 8;         // 0 or 8
    const float* aptr = x + ((size_t)(bb + lrow) * TT + t) * II + lc;
    const float* bptr = Wih + (size_t)(n0 + lrow) * II + lc;

    float acc[8][8];
#pragma unroll
    for (int i = 0; i < 8; i++)
#pragma unroll
        for (int j = 0; j < 8; j++) acc[i][j] = 0.0f;

    for (int kt = 0; kt < II; kt += 16) {
        float4 a0 = *(const float4*)(aptr + kt);
        float4 a1 = *(const float4*)(aptr + kt + 4);
        float4 b0 = *(const float4*)(bptr + kt);
        float4 b1 = *(const float4*)(bptr + kt + 4);
        As[lc + 0][lrow] = a0.x; As[lc + 1][lrow] = a0.y;
        As[lc + 2][lrow] = a0.z; As[lc + 3][lrow] = a0.w;
        As[lc + 4][lrow] = a1.x; As[lc + 5][lrow] = a1.y;
        As[lc + 6][lrow] = a1.z; As[lc + 7][lrow] = a1.w;
        Bs[lc + 0][lrow] = b0.x; Bs[lc + 1][lrow] = b0.y;
        Bs[lc + 2][lrow] = b0.z; Bs[lc + 3][lrow] = b0.w;
        Bs[lc + 4][lrow] = b1.x; Bs[lc + 5][lrow] = b1.y;
        Bs[lc + 6][lrow] = b1.z; Bs[lc + 7][lrow] = b1.w;
        __syncthreads();
#pragma unroll
        for (int k = 0; k < 16; k++) {
            float4 av0 = *(const float4*)&As[k][ty * 8];
            float4 av1 = *(const float4*)&As[k][ty * 8 + 4];
            float4 bv0 = *(const float4*)&Bs[k][tx * 8];
            float4 bv1 = *(const float4*)&Bs[k][tx * 8 + 4];
            float ar[8] = {av0.x, av0.y, av0.z, av0.w, av1.x, av1.y, av1.z, av1.w};
            float br[8] = {bv0.x, bv0.y, bv0.z, bv0.w, bv1.x, bv1.y, bv1.z, bv1.w};
#pragma unroll
            for (int i = 0; i < 8; i++)
#pragma unroll
                for (int j = 0; j < 8; j++)
                    acc[i][j] = fmaf(ar[i], br[j], acc[i][j]);
        }
        __syncthreads();
    }

    float bsum[8];
#pragma unroll
    for (int j = 0; j < 8; j++) {
        int n = n0 + tx * 8 + j;
        bsum[j] = bih[n] + bhh[n];
    }
#pragma unroll
    for (int i = 0; i < 8; i++) {
        size_t m = (size_t)(m0 + ty * 8 + i);
        float* crow = g_xproj + m * FOURH + n0 + tx * 8;
#pragma unroll
        for (int j = 0; j < 8; j++) crow[j] = acc[i][j] + bsum[j];
    }
}

// ---------------- encoder recurrent step ------------------------------------
// pre = xproj[t] + h @ Whh^T ; fused gates ; update c, h
// BM=64 (batch), BN=128 = 4 gates x 32 j, BK=16, 256 thr, TM=4, TN=8
__global__ __launch_bounds__(256, 1)
void enc_step_kernel(const float* __restrict__ Whh, int t) {
    const int j0 = blockIdx.x * 32;         // 32 j-tiles over H=1024
    const int b0 = blockIdx.y * 64;         // 4 b-tiles over B=256
    const float* __restrict__ hin  = g_henc[t & 1];
    float* __restrict__ hout       = g_henc[(t + 1) & 1];
    const float* __restrict__ xadd = g_xproj + (size_t)t * (BSZ * FOURH);

    __shared__ __align__(16) float As[16][64];
    __shared__ __align__(16) float Bs[16][132];

    const int tid = threadIdx.x;
    const int tx = tid & 15;
    const int ty = tid >> 4;

    // A-tile loader: 64x16, 1 float4 per thread
    const int arow = tid >> 2;              // 0..63
    const int ac   = (tid & 3) * 4;
    const float* aptr = hin + (size_t)(b0 + arow) * HH + ac;
    // B-tile loader: 128 mapped rows x 16, 2 float4 per thread
    const int brow = tid >> 1;              // 0..127
    const int bc   = (tid & 1) * 8;
    const int gate = brow >> 5;
    const int jlb  = brow & 31;
    const float* bptr = Whh + (size_t)(gate * HH + j0 + jlb) * HH + bc;

    float acc[4][8];
#pragma unroll
    for (int i = 0; i < 4; i++)
#pragma unroll
        for (int j = 0; j < 8; j++) acc[i][j] = 0.0f;

    for (int kt = 0; kt < HH; kt += 16) {
        float4 av = *(const float4*)(aptr + kt);
        As[ac + 0][arow] = av.x; As[ac + 1][arow] = av.y;
        As[ac + 2][arow] = av.z; As[ac + 3][arow] = av.w;
        float4 bv0 = *(const float4*)(bptr + kt);
        float4 bv1 = *(const float4*)(bptr + kt + 4);
        Bs[bc + 0][brow] = bv0.x; Bs[bc + 1][brow] = bv0.y;
        Bs[bc + 2][brow] = bv0.z; Bs[bc + 3][brow] = bv0.w;
        Bs[bc + 4][brow] = bv1.x; Bs[bc + 5][brow] = bv1.y;
        Bs[bc + 6][brow] = bv1.z; Bs[bc + 7][brow] = bv1.w;
        __syncthreads();
#pragma unroll
        for (int k = 0; k < 16; k++) {
            float4 a = *(const float4*)&As[k][ty * 4];
            float4 bv0r = *(const float4*)&Bs[k][tx * 8];
            float4 bv1r = *(const float4*)&Bs[k][tx * 8 + 4];
            float ar[4] = {a.x, a.y, a.z, a.w};
            float br[8] = {bv0r.x, bv0r.y, bv0r.z, bv0r.w,
                           bv1r.x, bv1r.y, bv1r.z, bv1r.w};
#pragma unroll
            for (int i = 0; i < 4; i++)
#pragma unroll
                for (int j = 0; j < 8; j++)
                    acc[i][j] = fmaf(ar[i], br[j], acc[i][j]);
        }
        __syncthreads();
    }

    // epilogue: add xproj, exchange through smem, compute gates
    __shared__ float preS[64][129];
#pragma unroll
    for (int i = 0; i < 4; i++) {
        int r = ty * 4 + i;
#pragma unroll
        for (int j = 0; j < 8; j++) {
            int ccol = tx * 8 + j;
            int g = ccol >> 5, jl = ccol & 31;
            float xa = xadd[(size_t)(b0 + r) * FOURH + g * HH + j0 + jl];
            preS[r][ccol] = acc[i][j] + xa;
        }
    }
    __syncthreads();
    {
        int r = tid >> 2;                // 0..63
        int jb = (tid & 3) * 8;
        int b = b0 + r;
#pragma unroll
        for (int i = 0; i < 8; i++) {
            int jl = jb + i;
            float iv = sigmoidf_(preS[r][jl]);
            float fv = sigmoidf_(preS[r][32 + jl]);
            float gv = tanhf(preS[r][64 + jl]);
            float ov = sigmoidf_(preS[r][96 + jl]);
            size_t idx = (size_t)b * HH + j0 + jl;
            float cn = fv * g_cenc[idx] + iv * gv;
            g_cenc[idx] = cn;
            hout[idx] = ov * tanhf(cn);
        }
    }
}

// ---------------- decoder recurrent step ------------------------------------
// pre = fixed + h @ W_rec^T ; gates ; update c, h ; write out reversed
// BM=32, BN=128 = 4 gates x 32 j, BK=16, 256 thr, TM=2, TN=8
__global__ __launch_bounds__(256, 1)
void dec_step_kernel(float* __restrict__ out, int t) {
    const int j0 = blockIdx.x * 32;         // 16 j-tiles over I=512
    const int b0 = blockIdx.y * 32;         // 8 b-tiles over B=256
    const float* __restrict__ hin = g_hdec[t & 1];
    float* __restrict__ hout      = g_hdec[(t + 1) & 1];

    __shared__ __align__(16) float As[16][32];
    __shared__ __align__(16) float Bs[16][132];

    const int tid = threadIdx.x;
    const int tx = tid & 15;
    const int ty = tid >> 4;

    const int arow = tid >> 3;              // 0..31
    const int ac   = (tid & 7) * 2;
    const float* aptr = hin + (size_t)(b0 + arow) * II + ac;
    const int brow = tid >> 1;              // 0..127
    const int bc   = (tid & 1) * 8;
    const int gate = brow >> 5;
    const int jlb  = brow & 31;
    const float* bptr = g_wrec + (size_t)(gate * II + j0 + jlb) * II + bc;

    float acc[2][8];
#pragma unroll
    for (int i = 0; i < 2; i++)
#pragma unroll
        for (int j = 0; j < 8; j++) acc[i][j] = 0.0f;

    for (int kt = 0; kt < II; kt += 16) {
        float2 av = *(const float2*)(aptr + kt);
        As[ac + 0][arow] = av.x; As[ac + 1][arow] = av.y;
        float4 bv0 = *(const float4*)(bptr + kt);
        float4 bv1 = *(const float4*)(bptr + kt + 4);
        Bs[bc + 0][brow] = bv0.x; Bs[bc + 1][brow] = bv0.y;
        Bs[bc + 2][brow] = bv0.z; Bs[bc + 3][brow] = bv0.w;
        Bs[bc + 4][brow] = bv1.x; Bs[bc + 5][brow] = bv1.y;
        Bs[bc + 6][brow] = bv1.z; Bs[bc + 7][brow] = bv1.w;
        __syncthreads();
#pragma unroll
        for (int k = 0; k < 16; k++) {
            float2 a = *(const float2*)&As[k][ty * 2];
            float4 bv0r = *(const float4*)&Bs[k][tx * 8];
            float4 bv1r = *(const float4*)&Bs[k][tx * 8 + 4];
            float ar[2] = {a.x, a.y};
            float br[8] = {bv0r.x, bv0r.y, bv0r.z, bv0r.w,
                           bv1r.x, bv1r.y, bv1r.z, bv1r.w};
#pragma unroll
            for (int i = 0; i < 2; i++)
#pragma unroll
                for (int j = 0; j < 8; j++)
                    acc[i][j] = fmaf(ar[i], br[j], acc[i][j]);
        }
        __syncthreads();
    }

    __shared__ float preS[32][129];
#pragma unroll
    for (int i = 0; i < 2; i++) {
        int r = ty * 2 + i;
#pragma unroll
        for (int j = 0; j < 8; j++) {
            int ccol = tx * 8 + j;
            int g = ccol >> 5, jl = ccol & 31;
            float fx = g_fixed[(size_t)(b0 + r) * FOURI + g * II + j0 + jl];
            preS[r][ccol] = acc[i][j] + fx;
        }
    }
    __syncthreads();
    {
        int r = tid >> 3;               // 0..31
        int jb = (tid & 7) * 4;
        int b = b0 + r;
#pragma unroll
        for (int i = 0; i < 4; i++) {
            int jl = jb + i;
            float iv = sigmoidf_(preS[r][jl]);
            float fv = sigmoidf_(preS[r][32 + jl]);
            float gv = tanhf(preS[r][64 + jl]);
            float ov = sigmoidf_(preS[r][96 + jl]);
            size_t idx = (size_t)b * II + j0 + jl;
            float cn = fv * g_cdec[idx] + iv * gv;
            g_cdec[idx] = cn;
            float hn = ov * tanhf(cn);
            hout[idx] = hn;
            out[((size_t)b * TT + (TT - 1 - t)) * II + j0 + jl] = hn;
        }
    }
}

// ---------------- generic small GEMM: C = act(A @ Bw^T + b1 [+ b2]) ---------
// BM=64, BN=128, BK=16, 256 thr, TM=4, TN=8. M%64==0, N%128==0, K%16==0.
template <bool RELU, bool HASB2>
__global__ __launch_bounds__(256, 1)
void gemm_bias_kernel(const float* __restrict__ A, int lda,
                      const float* __restrict__ Bw, int ldb,
                      const float* __restrict__ b1, const float* __restrict__ b2,
                      float* __restrict__ C, int ldc, int K) {
    const int n0 = blockIdx.x * 128;
    const int m0 = blockIdx.y * 64;

    __shared__ __align__(16) float As[16][64];
    __shared__ __align__(16) float Bs[16][132];

    const int tid = threadIdx.x;
    const int tx = tid & 15;
    const int ty = tid >> 4;

    const int arow = tid >> 2;
    const int ac   = (tid & 3) * 4;
    const float* aptr = A + (size_t)(m0 + arow) * lda + ac;
    const int brow = tid >> 1;
    const int bc   = (tid & 1) * 8;
    const float* bptr = Bw + (size_t)(n0 + brow) * ldb + bc;

    float acc[4][8];
#pragma unroll
    for (int i = 0; i < 4; i++)
#pragma unroll
        for (int j = 0; j < 8; j++) acc[i][j] = 0.0f;

    for (int kt = 0; kt < K; kt += 16) {
        float4 av = *(const float4*)(aptr + kt);
        As[ac + 0][arow] = av.x; As[ac + 1][arow] = av.y;
        As[ac + 2][arow] = av.z; As[ac + 3][arow] = av.w;
        float4 bv0 = *(const float4*)(bptr + kt);
        float4 bv1 = *(const float4*)(bptr + kt + 4);
        Bs[bc + 0][brow] = bv0.x; Bs[bc + 1][brow] = bv0.y;
        Bs[bc + 2][brow] = bv0.z; Bs[bc + 3][brow] = bv0.w;
        Bs[bc + 4][brow] = bv1.x; Bs[bc + 5][brow] = bv1.y;
        Bs[bc + 6][brow] = bv1.z; Bs[bc + 7][brow] = bv1.w;
        __syncthreads();
#pragma unroll
        for (int k = 0; k < 16; k++) {
            float4 a = *(const float4*)&As[k][ty * 4];
            float4 bv0r = *(const float4*)&Bs[k][tx * 8];
            float4 bv1r = *(const float4*)&Bs[k][tx * 8 + 4];
            float ar[4] = {a.x, a.y, a.z, a.w};
            float br[8] = {bv0r.x, bv0r.y, bv0r.z, bv0r.w,
                           bv1r.x, bv1r.y, bv1r.z, bv1r.w};
#pragma unroll
            for (int i = 0; i < 4; i++)
#pragma unroll
                for (int j = 0; j < 8; j++)
                    acc[i][j] = fmaf(ar[i], br[j], acc[i][j]);
        }
        __syncthreads();
    }

#pragma unroll
    for (int j = 0; j < 8; j++) {
        int n = n0 + tx * 8 + j;
        float bias = b1[n];
        if (HASB2) bias += b2[n];
#pragma unroll
        for (int i = 0; i < 4; i++) {
            float v = acc[i][j] + bias;
            if (RELU) v = fmaxf(v, 0.0f);
            C[(size_t)(m0 + ty * 4 + i) * ldc + n] = v;
        }
    }
}

// ---------------- launcher ---------------------------------------------------
extern "C" void kernel_launch(void* const* d_in, const int* in_sizes, int n_in,
                              void* d_out, int out_size) {
    const float* x        = (const float*)d_in[0];
    const float* enc_Wih  = (const float*)d_in[1];
    const float* enc_Whh  = (const float*)d_in[2];
    const float* enc_bih  = (const float*)d_in[3];
    const float* enc_bhh  = (const float*)d_in[4];
    const float* encfc_W  = (const float*)d_in[5];
    const float* encfc_b  = (const float*)d_in[6];
    const float* decfc_W  = (const float*)d_in[7];
    const float* decfc_b  = (const float*)d_in[8];
    const float* dec_Wih  = (const float*)d_in[9];
    const float* dec_Whh  = (const float*)d_in[10];
    const float* dec_bih  = (const float*)d_in[11];
    const float* dec_bhh  = (const float*)d_in[12];
    float* out = (float*)d_out;
    float* embd = out + (size_t)BSZ * TT * II;   // outputs first, then embd

    // scratch symbol addresses (cheap, capture-safe, recomputed every call)
    void *p_henc, *p_cenc, *p_hdec, *p_cdec, *p_dfh, *p_fixed;
    cudaGetSymbolAddress(&p_henc, g_henc);
    cudaGetSymbolAddress(&p_cenc, g_cenc);
    cudaGetSymbolAddress(&p_hdec, g_hdec);
    cudaGetSymbolAddress(&p_cdec, g_cdec);
    cudaGetSymbolAddress(&p_dfh, g_dfh);
    cudaGetSymbolAddress(&p_fixed, g_fixed);

    // zero initial states (only ping-pong buffer 0 of h; c fully)
    cudaMemsetAsync(p_henc, 0, (size_t)BSZ * HH * sizeof(float));
    cudaMemsetAsync(p_cenc, 0, (size_t)BSZ * HH * sizeof(float));
    cudaMemsetAsync(p_hdec, 0, (size_t)BSZ * II * sizeof(float));
    cudaMemsetAsync(p_cdec, 0, (size_t)BSZ * II * sizeof(float));

    // W_rec = dec_Wih[:, H:] + dec_Whh
    wrec_kernel<<<(FOURI * II + 255) / 256, 256>>>(dec_Wih, dec_Whh);

    // xproj[t][b][:] = x[b][t][:] @ enc_Wih^T + (bih + bhh)
    xproj_gemm<<<dim3(FOURH / 128, (TT * BSZ) / 128), 256>>>(x, enc_Wih, enc_bih, enc_bhh);

    // encoder recurrence
    for (int t = 0; t < TT; t++)
        enc_step_kernel<<<dim3(HH / 32, BSZ / 64), 256>>>(enc_Whh, t);

    // embd = relu(c_final @ encfc_W^T + encfc_b)   [256 x 256]
    gemm_bias_kernel<true, false><<<dim3(EE / 128, BSZ / 64), 256>>>(
        (const float*)p_cenc, HH, encfc_W, HH, encfc_b, nullptr, embd, EE, HH);

    // dec_first_hidden = relu(embd @ decfc_W^T + decfc_b)  [256 x 1024]
    gemm_bias_kernel<true, false><<<dim3(HH / 128, BSZ / 64), 256>>>(
        (const float*)embd, EE, decfc_W, EE, decfc_b, nullptr, (float*)p_dfh, HH, EE);

    // fixed = dfh @ dec_Wih[:, :H]^T + (dec_bih + dec_bhh)  [256 x 2048]
    gemm_bias_kernel<false, true><<<dim3(FOURI / 128, BSZ / 64), 256>>>(
        (const float*)p_dfh, HH, dec_Wih, HPI, dec_bih, dec_bhh, (float*)p_fixed, FOURI, HH);

    // decoder recurrence (writes outputs reversed)
    for (int t = 0; t < TT; t++)
        dec_step_kernel<<<dim3(II / 32, BSZ / 32), 256>>>(out, t);
}

// round 17
// speedup vs baseline: 1.0019x; 1.0002x over previous
#include <cuda_runtime.h>
#include <math.h>

// Problem dims
#define BSZ 256
#define TT  128
#define II  512
#define HH  1024
#define EE  256
// derived
#define FOURH 4096
#define FOURI 2048
#define HPI   1536   // H + I

// ---------------- scratch (static device allocations; no cudaMalloc) --------
__device__ float g_xproj[134217728];      // [T][B][4H] = 128*256*4096 floats (512MB)
__device__ float g_henc[2][BSZ * HH];     // encoder h ping-pong
__device__ float g_cenc[BSZ * HH];        // encoder c
__device__ float g_hdec[2][BSZ * II];     // decoder h ping-pong
__device__ float g_cdec[BSZ * II];        // decoder c
__device__ float g_wrec[FOURI * II];      // [2048][512] = dec_Wih[:,H:] + dec_Whh
__device__ float g_fixed[BSZ * FOURI];    // [256][2048] fixed decoder pre-activation
__device__ float g_dfh[BSZ * HH];         // [256][1024] dec_first_hidden

__device__ __forceinline__ float sigmoidf_(float x) {
    return 1.0f / (1.0f + expf(-x));
}

// ---------------- W_rec precompute ------------------------------------------
__global__ void wrec_kernel(const float* __restrict__ dWih,
                            const float* __restrict__ dWhh) {
    int i = blockIdx.x * blockDim.x + threadIdx.x;   // over 2048*512
    if (i < FOURI * II) {
        int j = i >> 9;          // row 0..2047
        int k = i & 511;         // col 0..511
        g_wrec[i] = dWih[j * HPI + HH + k] + dWhh[i];
    }
}

// ---------------- xproj GEMM: [32768 x 4096 x 512] --------------------------
// C row m = t*256 + b ;  A row = x[b][t][:]  (x is [B,T,I])
// BM=128, BN=128, BK=16, 256 threads, TM=TN=8
__global__ __launch_bounds__(256, 1)
void xproj_gemm(const float* __restrict__ x, const float* __restrict__ Wih,
                const float* __restrict__ bih, const float* __restrict__ bhh) {
    const int n0 = blockIdx.x * 128;        // over 4096
    const int m0 = blockIdx.y * 128;        // over 32768
    const int t  = m0 >> 8;                 // rows of a block share one t
    const int bb = m0 & 255;                // b base (0 or 128)

    __shared__ __align__(16) float As[16][132];
    __shared__ __align__(16) float Bs[16][132];

    const int tid = threadIdx.x;
    const int tx = tid & 15;
    const int ty = tid >> 4;

    const int lrow = tid >> 1;              // 0..127
    const int lc   = (tid & 1) * 8;         // 0 or 8
    const float* aptr = x + ((size_t)(bb + lrow) * TT + t) * II + lc;
    const float* bptr = Wih + (size_t)(n0 + lrow) * II + lc;

    float acc[8][8];
#pragma unroll
    for (int i = 0; i < 8; i++)
#pragma unroll
        for (int j = 0; j < 8; j++) acc[i][j] = 0.0f;

    for (int kt = 0; kt < II; kt += 16) {
        float4 a0 = *(const float4*)(aptr + kt);
        float4 a1 = *(const float4*)(aptr + kt + 4);
        float4 b0 = *(const float4*)(bptr + kt);
        float4 b1 = *(const float4*)(bptr + kt + 4);
        As[lc + 0][lrow] = a0.x; As[lc + 1][lrow] = a0.y;
        As[lc + 2][lrow] = a0.z; As[lc + 3][lrow] = a0.w;
        As[lc + 4][lrow] = a1.x; As[lc + 5][lrow] = a1.y;
        As[lc + 6][lrow] = a1.z; As[lc + 7][lrow] = a1.w;
        Bs[lc + 0][lrow] = b0.x; Bs[lc + 1][lrow] = b0.y;
        Bs[lc + 2][lrow] = b0.z; Bs[lc + 3][lrow] = b0.w;
        Bs[lc + 4][lrow] = b1.x; Bs[lc + 5][lrow] = b1.y;
        Bs[lc + 6][lrow] = b1.z; Bs[lc + 7][lrow] = b1.w;
        __syncthreads();
#pragma unroll
        for (int k = 0; k < 16; k++) {
            float4 av0 = *(const float4*)&As[k][ty * 8];
            float4 av1 = *(const float4*)&As[k][ty * 8 + 4];
            float4 bv0 = *(const float4*)&Bs[k][tx * 8];
            float4 bv1 = *(const float4*)&Bs[k][tx * 8 + 4];
            float ar[8] = {av0.x, av0.y, av0.z, av0.w, av1.x, av1.y, av1.z, av1.w};
            float br[8] = {bv0.x, bv0.y, bv0.z, bv0.w, bv1.x, bv1.y, bv1.z, bv1.w};
#pragma unroll
            for (int i = 0; i < 8; i++)
#pragma unroll
                for (int j = 0; j < 8; j++)
                    acc[i][j] = fmaf(ar[i], br[j], acc[i][j]);
        }
        __syncthreads();
    }

    float bsum[8];
#pragma unroll
    for (int j = 0; j < 8; j++) {
        int n = n0 + tx * 8 + j;
        bsum[j] = bih[n] + bhh[n];
    }
#pragma unroll
    for (int i = 0; i < 8; i++) {
        size_t m = (size_t)(m0 + ty * 8 + i);
        float* crow = g_xproj + m * FOURH + n0 + tx * 8;
#pragma unroll
        for (int j = 0; j < 8; j++) crow[j] = acc[i][j] + bsum[j];
    }
}

// ---------------- encoder recurrent step ------------------------------------
// pre = xproj[t] + h @ Whh^T ; fused gates ; update c, h
// BM=64 (batch), BN=128 = 4 gates x 32 j, BK=16, 256 thr, TM=4, TN=8
__global__ __launch_bounds__(256, 1)
void enc_step_kernel(const float* __restrict__ Whh, int t) {
    const int j0 = blockIdx.x * 32;         // 32 j-tiles over H=1024
    const int b0 = blockIdx.y * 64;         // 4 b-tiles over B=256
    const float* __restrict__ hin  = g_henc[t & 1];
    float* __restrict__ hout       = g_henc[(t + 1) & 1];
    const float* __restrict__ xadd = g_xproj + (size_t)t * (BSZ * FOURH);

    __shared__ __align__(16) float As[16][64];
    __shared__ __align__(16) float Bs[16][132];

    const int tid = threadIdx.x;
    const int tx = tid & 15;
    const int ty = tid >> 4;

    // A-tile loader: 64x16, 1 float4 per thread
    const int arow = tid >> 2;              // 0..63
    const int ac   = (tid & 3) * 4;
    const float* aptr = hin + (size_t)(b0 + arow) * HH + ac;
    // B-tile loader: 128 mapped rows x 16, 2 float4 per thread
    const int brow = tid >> 1;              // 0..127
    const int bc   = (tid & 1) * 8;
    const int gate = brow >> 5;
    const int jlb  = brow & 31;
    const float* bptr = Whh + (size_t)(gate * HH + j0 + jlb) * HH + bc;

    float acc[4][8];
#pragma unroll
    for (int i = 0; i < 4; i++)
#pragma unroll
        for (int j = 0; j < 8; j++) acc[i][j] = 0.0f;

    for (int kt = 0; kt < HH; kt += 16) {
        float4 av = *(const float4*)(aptr + kt);
        As[ac + 0][arow] = av.x; As[ac + 1][arow] = av.y;
        As[ac + 2][arow] = av.z; As[ac + 3][arow] = av.w;
        float4 bv0 = *(const float4*)(bptr + kt);
        float4 bv1 = *(const float4*)(bptr + kt + 4);
        Bs[bc + 0][brow] = bv0.x; Bs[bc + 1][brow] = bv0.y;
        Bs[bc + 2][brow] = bv0.z; Bs[bc + 3][brow] = bv0.w;
        Bs[bc + 4][brow] = bv1.x; Bs[bc + 5][brow] = bv1.y;
        Bs[bc + 6][brow] = bv1.z; Bs[bc + 7][brow] = bv1.w;
        __syncthreads();
#pragma unroll
        for (int k = 0; k < 16; k++) {
            float4 a = *(const float4*)&As[k][ty * 4];
            float4 bv0r = *(const float4*)&Bs[k][tx * 8];
            float4 bv1r = *(const float4*)&Bs[k][tx * 8 + 4];
            float ar[4] = {a.x, a.y, a.z, a.w};
            float br[8] = {bv0r.x, bv0r.y, bv0r.z, bv0r.w,
                           bv1r.x, bv1r.y, bv1r.z, bv1r.w};
#pragma unroll
            for (int i = 0; i < 4; i++)
#pragma unroll
                for (int j = 0; j < 8; j++)
                    acc[i][j] = fmaf(ar[i], br[j], acc[i][j]);
        }
        __syncthreads();
    }

    // epilogue: add xproj, exchange through smem, compute gates
    __shared__ float preS[64][129];
#pragma unroll
    for (int i = 0; i < 4; i++) {
        int r = ty * 4 + i;
#pragma unroll
        for (int j = 0; j < 8; j++) {
            int ccol = tx * 8 + j;
            int g = ccol >> 5, jl = ccol & 31;
            float xa = xadd[(size_t)(b0 + r) * FOURH + g * HH + j0 + jl];
            preS[r][ccol] = acc[i][j] + xa;
        }
    }
    __syncthreads();
    {
        int r = tid >> 2;                // 0..63
        int jb = (tid & 3) * 8;
        int b = b0 + r;
#pragma unroll
        for (int i = 0; i < 8; i++) {
            int jl = jb + i;
            float iv = sigmoidf_(preS[r][jl]);
            float fv = sigmoidf_(preS[r][32 + jl]);
            float gv = tanhf(preS[r][64 + jl]);
            float ov = sigmoidf_(preS[r][96 + jl]);
            size_t idx = (size_t)b * HH + j0 + jl;
            float cn = fv * g_cenc[idx] + iv * gv;
            g_cenc[idx] = cn;
            hout[idx] = ov * tanhf(cn);
        }
    }
}

// ---------------- decoder recurrent step ------------------------------------
// pre = fixed + h @ W_rec^T ; gates ; update c, h ; write out reversed
// BM=32, BN=128 = 4 gates x 32 j, BK=16, 256 thr, TM=2, TN=8
__global__ __launch_bounds__(256, 1)
void dec_step_kernel(float* __restrict__ out, int t) {
    const int j0 = blockIdx.x * 32;         // 16 j-tiles over I=512
    const int b0 = blockIdx.y * 32;         // 8 b-tiles over B=256
    const float* __restrict__ hin = g_hdec[t & 1];
    float* __restrict__ hout      = g_hdec[(t + 1) & 1];

    __shared__ __align__(16) float As[16][32];
    __shared__ __align__(16) float Bs[16][132];

    const int tid = threadIdx.x;
    const int tx = tid & 15;
    const int ty = tid >> 4;

    const int arow = tid >> 3;              // 0..31
    const int ac   = (tid & 7) * 2;
    const float* aptr = hin + (size_t)(b0 + arow) * II + ac;
    const int brow = tid >> 1;              // 0..127
    const int bc   = (tid & 1) * 8;
    const int gate = brow >> 5;
    const int jlb  = brow & 31;
    const float* bptr = g_wrec + (size_t)(gate * II + j0 + jlb) * II + bc;

    float acc[2][8];
#pragma unroll
    for (int i = 0; i < 2; i++)
#pragma unroll
        for (int j = 0; j < 8; j++) acc[i][j] = 0.0f;

    for (int kt = 0; kt < II; kt += 16) {
        float2 av = *(const float2*)(aptr + kt);
        As[ac + 0][arow] = av.x; As[ac + 1][arow] = av.y;
        float4 bv0 = *(const float4*)(bptr + kt);
        float4 bv1 = *(const float4*)(bptr + kt + 4);
        Bs[bc + 0][brow] = bv0.x; Bs[bc + 1][brow] = bv0.y;
        Bs[bc + 2][brow] = bv0.z; Bs[bc + 3][brow] = bv0.w;
        Bs[bc + 4][brow] = bv1.x; Bs[bc + 5][brow] = bv1.y;
        Bs[bc + 6][brow] = bv1.z; Bs[bc + 7][brow] = bv1.w;
        __syncthreads();
#pragma unroll
        for (int k = 0; k < 16; k++) {
            float2 a = *(const float2*)&As[k][ty * 2];
            float4 bv0r = *(const float4*)&Bs[k][tx * 8];
            float4 bv1r = *(const float4*)&Bs[k][tx * 8 + 4];
            float ar[2] = {a.x, a.y};
            float br[8] = {bv0r.x, bv0r.y, bv0r.z, bv0r.w,
                           bv1r.x, bv1r.y, bv1r.z, bv1r.w};
#pragma unroll
            for (int i = 0; i < 2; i++)
#pragma unroll
                for (int j = 0; j < 8; j++)
                    acc[i][j] = fmaf(ar[i], br[j], acc[i][j]);
        }
        __syncthreads();
    }

    __shared__ float preS[32][129];
#pragma unroll
    for (int i = 0; i < 2; i++) {
        int r = ty * 2 + i;
#pragma unroll
        for (int j = 0; j < 8; j++) {
            int ccol = tx * 8 + j;
            int g = ccol >> 5, jl = ccol & 31;
            float fx = g_fixed[(size_t)(b0 + r) * FOURI + g * II + j0 + jl];
            preS[r][ccol] = acc[i][j] + fx;
        }
    }
    __syncthreads();
    {
        int r = tid >> 3;               // 0..31
        int jb = (tid & 7) * 4;
        int b = b0 + r;
#pragma unroll
        for (int i = 0; i < 4; i++) {
            int jl = jb + i;
            float iv = sigmoidf_(preS[r][jl]);
            float fv = sigmoidf_(preS[r][32 + jl]);
            float gv = tanhf(preS[r][64 + jl]);
            float ov = sigmoidf_(preS[r][96 + jl]);
            size_t idx = (size_t)b * II + j0 + jl;
            float cn = fv * g_cdec[idx] + iv * gv;
            g_cdec[idx] = cn;
            float hn = ov * tanhf(cn);
            hout[idx] = hn;
            out[((size_t)b * TT + (TT - 1 - t)) * II + j0 + jl] = hn;
        }
    }
}

// ---------------- generic small GEMM: C = act(A @ Bw^T + b1 [+ b2]) ---------
// BM=64, BN=128, BK=16, 256 thr, TM=4, TN=8. M%64==0, N%128==0, K%16==0.
template <bool RELU, bool HASB2>
__global__ __launch_bounds__(256, 1)
void gemm_bias_kernel(const float* __restrict__ A, int lda,
                      const float* __restrict__ Bw, int ldb,
                      const float* __restrict__ b1, const float* __restrict__ b2,
                      float* __restrict__ C, int ldc, int K) {
    const int n0 = blockIdx.x * 128;
    const int m0 = blockIdx.y * 64;

    __shared__ __align__(16) float As[16][64];
    __shared__ __align__(16) float Bs[16][132];

    const int tid = threadIdx.x;
    const int tx = tid & 15;
    const int ty = tid >> 4;

    const int arow = tid >> 2;
    const int ac   = (tid & 3) * 4;
    const float* aptr = A + (size_t)(m0 + arow) * lda + ac;
    const int brow = tid >> 1;
    const int bc   = (tid & 1) * 8;
    const float* bptr = Bw + (size_t)(n0 + brow) * ldb + bc;

    float acc[4][8];
#pragma unroll
    for (int i = 0; i < 4; i++)
#pragma unroll
        for (int j = 0; j < 8; j++) acc[i][j] = 0.0f;

    for (int kt = 0; kt < K; kt += 16) {
        float4 av = *(const float4*)(aptr + kt);
        As[ac + 0][arow] = av.x; As[ac + 1][arow] = av.y;
        As[ac + 2][arow] = av.z; As[ac + 3][arow] = av.w;
        float4 bv0 = *(const float4*)(bptr + kt);
        float4 bv1 = *(const float4*)(bptr + kt + 4);
        Bs[bc + 0][brow] = bv0.x; Bs[bc + 1][brow] = bv0.y;
        Bs[bc + 2][brow] = bv0.z; Bs[bc + 3][brow] = bv0.w;
        Bs[bc + 4][brow] = bv1.x; Bs[bc + 5][brow] = bv1.y;
        Bs[bc + 6][brow] = bv1.z; Bs[bc + 7][brow] = bv1.w;
        __syncthreads();
#pragma unroll
        for (int k = 0; k < 16; k++) {
            float4 a = *(const float4*)&As[k][ty * 4];
            float4 bv0r = *(const float4*)&Bs[k][tx * 8];
            float4 bv1r = *(const float4*)&Bs[k][tx * 8 + 4];
            float ar[4] = {a.x, a.y, a.z, a.w};
            float br[8] = {bv0r.x, bv0r.y, bv0r.z, bv0r.w,
                           bv1r.x, bv1r.y, bv1r.z, bv1r.w};
#pragma unroll
            for (int i = 0; i < 4; i++)
#pragma unroll
                for (int j = 0; j < 8; j++)
                    acc[i][j] = fmaf(ar[i], br[j], acc[i][j]);
        }
        __syncthreads();
    }

#pragma unroll
    for (int j = 0; j < 8; j++) {
        int n = n0 + tx * 8 + j;
        float bias = b1[n];
        if (HASB2) bias += b2[n];
#pragma unroll
        for (int i = 0; i < 4; i++) {
            float v = acc[i][j] + bias;
            if (RELU) v = fmaxf(v, 0.0f);
            C[(size_t)(m0 + ty * 4 + i) * ldc + n] = v;
        }
    }
}

// ---------------- launcher ---------------------------------------------------
extern "C" void kernel_launch(void* const* d_in, const int* in_sizes, int n_in,
                              void* d_out, int out_size) {
    const float* x        = (const float*)d_in[0];
    const float* enc_Wih  = (const float*)d_in[1];
    const float* enc_Whh  = (const float*)d_in[2];
    const float* enc_bih  = (const float*)d_in[3];
    const float* enc_bhh  = (const float*)d_in[4];
    const float* encfc_W  = (const float*)d_in[5];
    const float* encfc_b  = (const float*)d_in[6];
    const float* decfc_W  = (const float*)d_in[7];
    const float* decfc_b  = (const float*)d_in[8];
    const float* dec_Wih  = (const float*)d_in[9];
    const float* dec_Whh  = (const float*)d_in[10];
    const float* dec_bih  = (const float*)d_in[11];
    const float* dec_bhh  = (const float*)d_in[12];
    float* out = (float*)d_out;
    float* embd = out + (size_t)BSZ * TT * II;   // outputs first, then embd

    // scratch symbol addresses (cheap, capture-safe, recomputed every call)
    void *p_henc, *p_cenc, *p_hdec, *p_cdec, *p_dfh, *p_fixed;
    cudaGetSymbolAddress(&p_henc, g_henc);
    cudaGetSymbolAddress(&p_cenc, g_cenc);
    cudaGetSymbolAddress(&p_hdec, g_hdec);
    cudaGetSymbolAddress(&p_cdec, g_cdec);
    cudaGetSymbolAddress(&p_dfh, g_dfh);
    cudaGetSymbolAddress(&p_fixed, g_fixed);

    // zero initial states (only ping-pong buffer 0 of h; c fully)
    cudaMemsetAsync(p_henc, 0, (size_t)BSZ * HH * sizeof(float));
    cudaMemsetAsync(p_cenc, 0, (size_t)BSZ * HH * sizeof(float));
    cudaMemsetAsync(p_hdec, 0, (size_t)BSZ * II * sizeof(float));
    cudaMemsetAsync(p_cdec, 0, (size_t)BSZ * II * sizeof(float));

    // W_rec = dec_Wih[:, H:] + dec_Whh
    wrec_kernel<<<(FOURI * II + 255) / 256, 256>>>(dec_Wih, dec_Whh);

    // xproj[t][b][:] = x[b][t][:] @ enc_Wih^T + (bih + bhh)
    xproj_gemm<<<dim3(FOURH / 128, (TT * BSZ) / 128), 256>>>(x, enc_Wih, enc_bih, enc_bhh);

    // encoder recurrence
    for (int t = 0; t < TT; t++)
        enc_step_kernel<<<dim3(HH / 32, BSZ / 64), 256>>>(enc_Whh, t);

    // embd = relu(c_final @ encfc_W^T + encfc_b)   [256 x 256]
    gemm_bias_kernel<true, false><<<dim3(EE / 128, BSZ / 64), 256>>>(
        (const float*)p_cenc, HH, encfc_W, HH, encfc_b, nullptr, embd, EE, HH);

    // dec_first_hidden = relu(embd @ decfc_W^T + decfc_b)  [256 x 1024]
    gemm_bias_kernel<true, false><<<dim3(HH / 128, BSZ / 64), 256>>>(
        (const float*)embd, EE, decfc_W, EE, decfc_b, nullptr, (float*)p_dfh, HH, EE);

    // fixed = dfh @ dec_Wih[:, :H]^T + (dec_bih + dec_bhh)  [256 x 2048]
    gemm_bias_kernel<false, true><<<dim3(FOURI / 128, BSZ / 64), 256>>>(
        (const float*)p_dfh, HH, dec_Wih, HPI, dec_bih, dec_bhh, (float*)p_fixed, FOURI, HH);

    // decoder recurrence (writes outputs reversed)
    for (int t = 0; t < TT; t++)
        dec_step_kernel<<<dim3(II / 32, BSZ / 32), 256>>>(out, t);
}